// round 17
// baseline (speedup 1.0000x reference)
#include <cuda_runtime.h>
#include <cstdint>
#include <math.h>

#define BB 8192
#define DD 128
#define NB 64                   // 128-row bands
#define TM 128
#define TNH 64                  // tile-half column width
#define CHUNK 8                 // tile-halves per block
#define NTILES 4160             // 2*(64*65/2)
#define NBLK (NTILES / CHUNK)   // 520
#define NTHREADS 256
#define RCAP 4                  // row-side slots per (row,bj,h,thslot)
#define CCAP 12                 // col-side slots per (col,bi)

#define INV_T 14.2857142857142857f
#define MAXS  14.2857142857142857f
#define LOG2E 1.44269504088896340736f
#define QSCALE (1.0f / 16129.0f)
#define SIM_SCALE (INV_T * QSCALE)

// S(bi) = number of band-pairs before row bi (bi-major upper triangle)
#define SFUN(b) ((b) * NB - ((b) * ((b) - 1)) / 2)

static __device__ uint32_t g_enormq[BB * 32];
static __device__ int   g_lab[BB];
static __device__ float g_rowseg[(size_t)BB * NB * 2 * 8 * RCAP];   // 134 MB
static __device__ int   g_rowcnt[BB * NB * 2 * 8];                  // 33.5 MB
static __device__ float g_colseg[(size_t)BB * NB * CCAP];           // 25 MB
static __device__ int   g_colcnt[BB * NB];                          // 2 MB
static __device__ float g_negrowpart[BB * NB * 2];                  // 4 MB
static __device__ float g_colpart[BB * NB];                         // 2 MB
static __device__ int   g_gridcnt;
static __device__ float g_row_loss[BB];
static __device__ int   g_row_cnt[BB];
static __device__ int   g_lab64;

// ---------------- helpers ----------------
__device__ __forceinline__ uint32_t smem_u32(const void* p) {
    uint32_t a;
    asm("{ .reg .u64 t; cvta.to.shared.u64 t, %1; cvt.u32.u64 %0, t; }"
        : "=r"(a) : "l"(p));
    return a;
}
__device__ __forceinline__ void cpa16(uint32_t s, const void* g) {
    asm volatile("cp.async.cg.shared.global [%0], [%1], 16;" :: "r"(s), "l"(g));
}
#define CPA_COMMIT() asm volatile("cp.async.commit_group;" ::: "memory")
#define CPA_WAIT1()  asm volatile("cp.async.wait_group 1;" ::: "memory")
#define CPA_WAIT0()  asm volatile("cp.async.wait_group 0;" ::: "memory")

__device__ __forceinline__ void ldsm4(uint32_t* r, uint32_t addr) {
    asm volatile("ldmatrix.sync.aligned.m8n8.x4.shared.b16 {%0,%1,%2,%3}, [%4];"
                 : "=r"(r[0]), "=r"(r[1]), "=r"(r[2]), "=r"(r[3]) : "r"(addr));
}
__device__ __forceinline__ void imma16832(int* c, const uint32_t* a,
                                          uint32_t b0, uint32_t b1) {
    asm volatile(
        "mma.sync.aligned.m16n8k32.row.col.s32.s8.s8.s32 "
        "{%0,%1,%2,%3},{%4,%5,%6,%7},{%8,%9},{%0,%1,%2,%3};"
        : "+r"(c[0]), "+r"(c[1]), "+r"(c[2]), "+r"(c[3])
        : "r"(a[0]), "r"(a[1]), "r"(a[2]), "r"(a[3]), "r"(b0), "r"(b1));
}
__device__ __forceinline__ float warp_sum(float v) {
    #pragma unroll
    for (int off = 16; off > 0; off >>= 1)
        v += __shfl_xor_sync(0xFFFFFFFFu, v, off);
    return v;
}
__device__ __forceinline__ int warp_sum_i(int v) {
    #pragma unroll
    for (int off = 16; off > 0; off >>= 1)
        v += __shfl_xor_sync(0xFFFFFFFFu, v, off);
    return v;
}
__device__ __forceinline__ float ex2f(float t) {
    float e;
    asm("ex2.approx.f32 %0, %1;" : "=f"(e) : "f"(t));
    return e;
}
__device__ __forceinline__ int bi_from_p(int p, int start) {
    int bi = start;
    while (bi < NB - 1 && SFUN(bi + 1) <= p) bi++;
    return bi;
}

// ---------------------------------------------------------------------------
// Kernel 0: detect label dtype
// ---------------------------------------------------------------------------
__global__ void detect_kernel(const unsigned int* __restrict__ w) {
    __shared__ int any;
    if (threadIdx.x == 0) any = 0;
    __syncthreads();
    int loc = 0;
    for (int i = threadIdx.x; i < BB / 2; i += blockDim.x)
        loc |= (w[2 * i + 1] != 0u);
    if (loc) atomicOr(&any, 1);
    __syncthreads();
    if (threadIdx.x == 0) g_lab64 = (any == 0) ? 1 : 0;
}

// ---------------------------------------------------------------------------
// Kernel 1: L2-normalize rows -> int8; labels -> int32; zero grid counter.
// ---------------------------------------------------------------------------
__global__ void norm_kernel(const float* __restrict__ emb,
                            const void* __restrict__ labels) {
    int warp = threadIdx.x >> 5;
    int lane = threadIdx.x & 31;
    int row = blockIdx.x * 8 + warp;
    if (row >= BB) return;

    const float4* src = reinterpret_cast<const float4*>(emb) + (size_t)row * (DD / 4);
    float4 v = src[lane];
    float ss = v.x * v.x + v.y * v.y + v.z * v.z + v.w * v.w;
    ss = warp_sum(ss);
    float inv = 127.0f / fmaxf(sqrtf(ss), 1e-12f);
    int q0 = __float2int_rn(v.x * inv);
    int q1 = __float2int_rn(v.y * inv);
    int q2 = __float2int_rn(v.z * inv);
    int q3 = __float2int_rn(v.w * inv);
    uint32_t packed = (uint32_t)(q0 & 0xFF) | ((uint32_t)(q1 & 0xFF) << 8) |
                      ((uint32_t)(q2 & 0xFF) << 16) | ((uint32_t)(q3 & 0xFF) << 24);
    g_enormq[(size_t)row * 32 + lane] = packed;
    if (lane == 0) {
        int lv;
        if (g_lab64) lv = (int)((const long long*)labels)[row];
        else         lv = ((const int*)labels)[row];
        g_lab[row] = lv;
        if (row == 0) g_gridcnt = 0;
    }
}

// ---------------------------------------------------------------------------
// SMEM layout (bytes from 256-aligned base)
// ---------------------------------------------------------------------------
#define AS_OFF(a)  ((a) * 16384)            // 2 x 16 KB
#define BS_OFF(b)  (32768 + (b) * 8192)     // 2 x 8 KB
#define LABJ_OFF   49152                    // int [2][64]
#define NEGP_OFF   49664                    // float [128][8]
#define COLP_OFF   53760                    // float [64]
#define CPC_OFF    54016                    // int [64]
#define CPV_OFF    54272                    // float [64][CCAP]
#define SMEM_NEED  (54272 + 64 * CCAP * 4 + 512)

// ---------------------------------------------------------------------------
// Kernel 2: symmetric s8 IMMA Gram. Only band-pairs bj >= bi; each entry
// feeds row i (row side) and, for off-diag tiles, row j (col side).
// ---------------------------------------------------------------------------
__global__ __launch_bounds__(NTHREADS, 3)
void main_kernel() {
    extern __shared__ char dyn_smem[];
    char* base = (char*)(((uintptr_t)dyn_smem + 255) & ~(uintptr_t)255);
    uint32_t sb = smem_u32(base);
    int* labJ = (int*)(base + LABJ_OFF);
    float* negp = (float*)(base + NEGP_OFF);
    float* colp = (float*)(base + COLP_OFF);
    int* colPosCnt = (int*)(base + CPC_OFF);
    float* colPosVal = (float*)(base + CPV_OFF);

    const int tid = threadIdx.x;
    const int lane = tid & 31;
    const int wid = tid >> 5;
    const int wfm = wid & 3;
    const int wfn = wid >> 2;
    const int m0w = wfm * 32;
    const int n0w = wfn * 32;
    const int thslot = wfn * 4 + (lane & 3);
    const char* gsrc = (const char*)g_enormq;

    // tile 0 ids
    int t = blockIdx.x * CHUNK;
    int p = t >> 1, h = t & 1;
    int bi = bi_from_p(p, 0);
    int bj = bi + (p - SFUN(bi));
    int i0 = bi * TM;
    int abuf = 0;

    // preamble: A(bi) -> abuf0, B(tile0)+labJ -> buf0
    {
        #pragma unroll
        for (int tt = 0; tt < 4; tt++) {
            int idx = tid + tt * 256;
            int r = idx >> 3, c = idx & 7;
            uint32_t d = sb + AS_OFF(0) + r * 128 + ((c ^ (r & 7)) << 4);
            cpa16(d, gsrc + (size_t)(i0 + r) * 128 + c * 16);
        }
        int j0 = bj * TM + h * TNH;
        #pragma unroll
        for (int tt = 0; tt < 2; tt++) {
            int idx = tid + tt * 256;
            int r = idx >> 3, c = idx & 7;
            uint32_t d = sb + BS_OFF(0) + r * 128 + ((c ^ (r & 7)) << 4);
            cpa16(d, gsrc + (size_t)(j0 + r) * 128 + c * 16);
        }
        if (tid < TNH) labJ[tid] = g_lab[j0 + tid];
        CPA_COMMIT();
    }
    if (tid < 64) { colp[tid] = 0.0f; colPosCnt[tid] = 0; }

    // fixed per-thread row-local ids; labels reloaded on bi change
    int rloc[2][2], iglab[2][2];
    #pragma unroll
    for (int mi = 0; mi < 2; mi++)
        #pragma unroll
        for (int rh = 0; rh < 2; rh++) {
            rloc[mi][rh] = m0w + mi * 16 + (lane >> 2) + rh * 8;
            iglab[mi][rh] = g_lab[i0 + rloc[mi][rh]];
        }

    uint32_t addrAbase[2];
    addrAbase[0] = sb + AS_OFF(0);
    addrAbase[1] = sb + AS_OFF(1);
    const int rowA_lo = m0w + (lane & 15);
    const int rxA = rowA_lo & 7;
    int rowB[2];
    #pragma unroll
    for (int nii = 0; nii < 2; nii++)
        rowB[nii] = n0w + nii * 16 + (lane & 7) + ((lane & 16) >> 1);

    for (int k = 0; k < CHUNK; k++) {
        const int buf = k & 1;
        const int j0 = bj * TM + h * TNH;
        const bool offdiag = (bi != bj);

        // prefetch next tile (B always; A iff band changes)
        int nbi = bi, nbj = bj, nh = h;
        bool aswap = false;
        if (k + 1 < CHUNK) {
            int tn = t + 1;
            int pn = tn >> 1;
            nh = tn & 1;
            nbi = bi_from_p(pn, bi);
            nbj = nbi + (pn - SFUN(nbi));
            int nb = (k + 1) & 1;
            int nj0 = nbj * TM + nh * TNH;
            #pragma unroll
            for (int tt = 0; tt < 2; tt++) {
                int idx = tid + tt * 256;
                int r = idx >> 3, c = idx & 7;
                uint32_t d = sb + BS_OFF(nb) + r * 128 + ((c ^ (r & 7)) << 4);
                cpa16(d, gsrc + (size_t)(nj0 + r) * 128 + c * 16);
            }
            if (tid < TNH) labJ[nb * TNH + tid] = g_lab[nj0 + tid];
            if (nbi != bi) {
                aswap = true;
                int ni0 = nbi * TM;
                #pragma unroll
                for (int tt = 0; tt < 4; tt++) {
                    int idx = tid + tt * 256;
                    int r = idx >> 3, c = idx & 7;
                    uint32_t d = sb + AS_OFF(abuf ^ 1) + r * 128 + ((c ^ (r & 7)) << 4);
                    cpa16(d, gsrc + (size_t)(ni0 + r) * 128 + c * 16);
                }
            }
            CPA_COMMIT();
            CPA_WAIT1();
        } else {
            CPA_WAIT0();
        }
        __syncthreads();

        // ---- MMA 128x64x128 ----
        int acc[2][4][4];
        #pragma unroll
        for (int mi = 0; mi < 2; mi++)
            #pragma unroll
            for (int ni = 0; ni < 4; ni++)
                #pragma unroll
                for (int cc = 0; cc < 4; cc++) acc[mi][ni][cc] = 0;

        uint32_t aB = addrAbase[abuf];
        #pragma unroll
        for (int ks = 0; ks < 4; ks++) {
            uint32_t Areg[2][4];
            #pragma unroll
            for (int mi = 0; mi < 2; mi++) {
                int chunkA = ks * 2 + (lane >> 4);
                ldsm4(Areg[mi], aB + (rowA_lo + mi * 16) * 128 + ((chunkA ^ rxA) << 4));
            }
            uint32_t Breg[2][4];
            #pragma unroll
            for (int nii = 0; nii < 2; nii++) {
                int chunk = ks * 2 + ((lane >> 3) & 1);
                uint32_t addr = sb + BS_OFF(buf) + rowB[nii] * 128 +
                                ((chunk ^ (rowB[nii] & 7)) << 4);
                ldsm4(Breg[nii], addr);
            }
            #pragma unroll
            for (int mi = 0; mi < 2; mi++)
                #pragma unroll
                for (int ni = 0; ni < 4; ni++)
                    imma16832(acc[mi][ni], Areg[mi],
                              Breg[ni >> 1][(ni & 1) * 2],
                              Breg[ni >> 1][(ni & 1) * 2 + 1]);
        }

        // ---- epilogue: row side (register slots) + col side (smem) ----
        float negacc[2][2] = {{0.0f, 0.0f}, {0.0f, 0.0f}};
        float colacc[8] = {0, 0, 0, 0, 0, 0, 0, 0};
        int pcnt[2][2] = {{0, 0}, {0, 0}};

        #pragma unroll
        for (int ni = 0; ni < 4; ni++) {
            int c0l = n0w + ni * 8 + 2 * (lane & 3);
            int lj0 = labJ[buf * TNH + c0l];
            int lj1 = labJ[buf * TNH + c0l + 1];
            int jg0 = j0 + c0l;
            #pragma unroll
            for (int mi = 0; mi < 2; mi++) {
                #pragma unroll
                for (int rh = 0; rh < 2; rh++) {
                    float v0 = __int2float_rn(acc[mi][ni][rh * 2 + 0]);
                    float v1 = __int2float_rn(acc[mi][ni][rh * 2 + 1]);
                    float e0 = ex2f(fmaf(v0, SIM_SCALE * LOG2E, -MAXS * LOG2E));
                    float e1 = ex2f(fmaf(v1, SIM_SCALE * LOG2E, -MAXS * LOG2E));
                    negacc[mi][rh] += e0 + e1;
                    colacc[ni * 2]     += e0;
                    colacc[ni * 2 + 1] += e1;
                    int ml = iglab[mi][rh];
                    int ig = i0 + rloc[mi][rh];
                    if (lj0 == ml) {
                        negacc[mi][rh] -= e0;
                        colacc[ni * 2] -= e0;
                        if (jg0 != ig) {
                            int c = pcnt[mi][rh];
                            if (c < RCAP) {
                                size_t bx = ((((size_t)ig * NB + bj) * 2 + h) * 8 + thslot) * RCAP + c;
                                g_rowseg[bx] = v0 * SIM_SCALE;
                            }
                            pcnt[mi][rh] = c + 1;
                            if (offdiag) {
                                int slot = atomicAdd(&colPosCnt[c0l], 1);
                                if (slot < CCAP)
                                    colPosVal[c0l * CCAP + slot] = v0 * SIM_SCALE;
                            }
                        }
                    }
                    if (lj1 == ml) {
                        negacc[mi][rh] -= e1;
                        colacc[ni * 2 + 1] -= e1;
                        if (jg0 + 1 != ig) {
                            int c = pcnt[mi][rh];
                            if (c < RCAP) {
                                size_t bx = ((((size_t)ig * NB + bj) * 2 + h) * 8 + thslot) * RCAP + c;
                                g_rowseg[bx] = v1 * SIM_SCALE;
                            }
                            pcnt[mi][rh] = c + 1;
                            if (offdiag) {
                                int slot = atomicAdd(&colPosCnt[c0l + 1], 1);
                                if (slot < CCAP)
                                    colPosVal[(c0l + 1) * CCAP + slot] = v1 * SIM_SCALE;
                            }
                        }
                    }
                }
            }
        }

        // row counts + negp partials
        #pragma unroll
        for (int mi = 0; mi < 2; mi++)
            #pragma unroll
            for (int rh = 0; rh < 2; rh++) {
                int rl = rloc[mi][rh];
                negp[rl * 8 + thslot] = negacc[mi][rh];
                int c = pcnt[mi][rh];
                g_rowcnt[(((i0 + rl) * NB + bj) * 2 + h) * 8 + thslot] =
                    (c > RCAP) ? RCAP : c;
            }
        // col partial sums into smem
        if (offdiag) {
            #pragma unroll
            for (int ix = 0; ix < 8; ix++) {
                int c = n0w + (ix >> 1) * 8 + 2 * (lane & 3) + (ix & 1);
                atomicAdd(&colp[c], colacc[ix]);
            }
        }
        __syncthreads();

        if (tid < TM) {
            float tot = 0.0f;
            #pragma unroll
            for (int s = 0; s < 8; s++) tot += negp[tid * 8 + s];
            g_negrowpart[((i0 + tid) * NB + bj) * 2 + h] = tot;
        }
        if (tid < 64 && offdiag) {
            int jg = j0 + tid;
            g_colpart[jg * NB + bi] = colp[tid];
            int cc = colPosCnt[tid];
            if (cc > CCAP) cc = CCAP;
            g_colcnt[jg * NB + bi] = cc;
            for (int c = 0; c < cc; c++)
                g_colseg[(size_t)(jg * NB + bi) * CCAP + c] = colPosVal[tid * CCAP + c];
        }
        __syncthreads();
        if (tid < 64) { colp[tid] = 0.0f; colPosCnt[tid] = 0; }

        // rotate ids
        if (k + 1 < CHUNK) {
            if (aswap) {
                abuf ^= 1;
                bi = nbi;
                i0 = bi * TM;
                #pragma unroll
                for (int mi = 0; mi < 2; mi++)
                    #pragma unroll
                    for (int rh = 0; rh < 2; rh++)
                        iglab[mi][rh] = g_lab[i0 + rloc[mi][rh]];
            }
            bj = nbj; h = nh; t++;
        }
    }
}

// ---------------------------------------------------------------------------
// Kernel 3: finalize — per-row negsum + softplus over stashed positives,
//           then grid-last final reduction.
// ---------------------------------------------------------------------------
__global__ void finalize_kernel(float* __restrict__ out) {
    __shared__ int s_gridlast;
    int wid = threadIdx.x >> 5;
    int lane = threadIdx.x & 31;
    int row = blockIdx.x * 8 + wid;
    int br = row >> 7;

    // negsum
    float ns = 0.0f;
    int nrow = (NB - br) * 2;
    for (int idx = lane; idx < nrow; idx += 32) {
        int bj = br + (idx >> 1);
        int hh = idx & 1;
        ns += g_negrowpart[(row * NB + bj) * 2 + hh];
    }
    for (int idx = lane; idx < br; idx += 32)
        ns += g_colpart[row * NB + idx];
    ns = warp_sum(ns);

    float nl = __logf(fmaxf(ns, 1e-30f)) + MAXS;
    float part = 0.0f;
    int cnt = 0;
    // row-side positives
    int ncomb = (NB - br) * 16;
    for (int idx = lane; idx < ncomb; idx += 32) {
        int bj = br + (idx >> 4);
        int rem = idx & 15;
        int hh = rem >> 3;
        int ts = rem & 7;
        int cbase = ((row * NB + bj) * 2 + hh) * 8 + ts;
        int c = g_rowcnt[cbase];
        cnt += c;
        const float* sp = g_rowseg + (size_t)cbase * RCAP;
        for (int cc = 0; cc < c; cc++)
            part += log1pf(__expf(nl - sp[cc]));
    }
    // col-side positives
    for (int idx = lane; idx < br; idx += 32) {
        int c = g_colcnt[row * NB + idx];
        cnt += c;
        const float* sp = g_colseg + (size_t)(row * NB + idx) * CCAP;
        for (int cc = 0; cc < c; cc++)
            part += log1pf(__expf(nl - sp[cc]));
    }
    part = warp_sum(part);
    cnt = warp_sum_i(cnt);
    if (lane == 0) {
        bool valid = (cnt > 0 && ns > 0.0f);
        g_row_loss[row] = valid ? part : 0.0f;
        g_row_cnt[row] = valid ? cnt : 0;
    }
    __threadfence();
    __syncthreads();

    if (threadIdx.x == 0) {
        int old = atomicAdd(&g_gridcnt, 1);
        s_gridlast = (old == (BB / 8) - 1) ? 1 : 0;
    }
    __syncthreads();
    if (!s_gridlast) return;
    __threadfence();

    {
        __shared__ double ssum[256];
        __shared__ long long scnt[256];
        int tid = threadIdx.x;
        double s = 0.0;
        long long c = 0;
        for (int i = tid; i < BB; i += 256) {
            s += (double)g_row_loss[i];
            c += (long long)g_row_cnt[i];
        }
        ssum[tid] = s; scnt[tid] = c;
        __syncthreads();
        for (int off = 128; off > 0; off >>= 1) {
            if (tid < off) { ssum[tid] += ssum[tid + off]; scnt[tid] += scnt[tid + off]; }
            __syncthreads();
        }
        if (tid == 0)
            out[0] = (scnt[0] > 0) ? (float)(ssum[0] / (double)scnt[0]) : 0.0f;
    }
}

// ---------------------------------------------------------------------------
extern "C" void kernel_launch(void* const* d_in, const int* in_sizes, int n_in,
                              void* d_out, int out_size) {
    const float* emb = (const float*)d_in[0];
    const void* labels = d_in[1];
    float* out = (float*)d_out;
    (void)in_sizes; (void)n_in; (void)out_size;

    cudaFuncSetAttribute(main_kernel, cudaFuncAttributeMaxDynamicSharedMemorySize,
                         SMEM_NEED);

    detect_kernel<<<1, 256>>>((const unsigned int*)labels);
    norm_kernel<<<BB / 8, 256>>>(emb, labels);
    main_kernel<<<NBLK, NTHREADS, SMEM_NEED>>>();
    finalize_kernel<<<BB / 8, 256>>>(out);
}